// round 6
// baseline (speedup 1.0000x reference)
#include <cuda_runtime.h>
#include <cstdint>

// B=8, C=16, H=512, W=512, M=N=15
//   K:     [128, 16, 16]  f32
//   basis: [262144, 16, 16] f32, separable: basis[h*W+w,p,q] = Bu[h,p]*Bv[w,q]
//   out:   [128, 512, 512] f32
//
// Bu[h,p] = sum_q basis[h*W, p, q]; Bv[w,q] = sum_p basis[w, p, q]
// T[bc,p,w] = sum_q K[bc,p,q]*Bv[w,q];  out[bc,h,w] = sum_p Bu[h,p]*T[bc,p,w]

#define HH 512
#define WW 512
#define PP 16
#define QQ 16
#define BC 128
#define ROWS 128

__device__ float g_But[PP * HH];        // Bu transposed: [p][h], 32 KB
__device__ float g_T[BC * PP * WW];     // T: [bc][p][w], 4 MB (L2-resident)

__device__ __forceinline__ unsigned long long pk(float a, float b) {
    unsigned long long r;
    asm("mov.b64 %0, {%1, %2};" : "=l"(r) : "f"(a), "f"(b));
    return r;
}
__device__ __forceinline__ void fma2(unsigned long long& d, unsigned long long a,
                                     unsigned long long b) {
    asm("fma.rn.f32x2 %0, %1, %2, %0;" : "+l"(d) : "l"(a), "l"(b));
}
__device__ __forceinline__ void unpk(unsigned long long v, float& a, float& b) {
    asm("mov.b64 {%0, %1}, %2;" : "=f"(a), "=f"(b) : "l"(v));
}

// ---------------------------------------------------------------------------
// Kernel P (single pre-pass, 320 blocks x 256 threads):
//   blocks 0..255  : (wb = blk>>2, g = blk&3). Compute Bv for w-rows
//                    [8wb, 8wb+8) via warp-per-row shfl reduction, then
//                    T[bc, :, w] for bc in [32g, 32g+32) from smem-staged K.
//   blocks 256..319: Bu extraction, warp-per-h-row (h = (blk-256)*8 + warp).
// ---------------------------------------------------------------------------
__global__ __launch_bounds__(256) void prepass(const float* __restrict__ K,
                                               const float* __restrict__ basis) {
    int tid = threadIdx.x;
    int warp = tid >> 5, lane = tid & 31;

    if (blockIdx.x >= 256) {
        // ---- Bu extraction ----
        int h = (blockIdx.x - 256) * 8 + warp;
        const float4* r4 = reinterpret_cast<const float4*>(basis + (size_t)h * WW * (PP * QQ));
        float4 a = r4[lane * 2];
        float4 b = r4[lane * 2 + 1];
        float s = (a.x + a.y) + (a.z + a.w) + (b.x + b.y) + (b.z + b.w);
        s += __shfl_xor_sync(0xffffffffu, s, 1);   // lanes (2k,2k+1) cover p=k
        if ((lane & 1) == 0) g_But[(lane >> 1) * HH + h] = s;
        return;
    }

    // ---- Bv + T slice ----
    int wb = blockIdx.x >> 2;       // 0..63 -> w0 = 8*wb
    int g  = blockIdx.x & 3;        // bc group: [32g, 32g+32)
    int w0 = wb * 8;

    __shared__ float sK[32 * PP * QQ];   // 32 KB
    __shared__ float sBv[8][QQ];

    // Stage K for 32 bc (coalesced float4)
    {
        const float4* src = reinterpret_cast<const float4*>(K + (size_t)g * 32 * PP * QQ);
        float4* dst = reinterpret_cast<float4*>(sK);
        #pragma unroll
        for (int i = 0; i < 8; ++i) dst[tid + 256 * i] = src[tid + 256 * i];
    }

    // Bv rows: warp r handles w = w0 + r
    {
        const float4* r4 = reinterpret_cast<const float4*>(basis + (size_t)(w0 + warp) * (PP * QQ));
        float4 a = r4[lane * 2];
        float4 b = r4[lane * 2 + 1];
        // lane l: p = l>>1, q = (l&1)*8 + j; butterfly over p (offsets 2..16)
        #pragma unroll
        for (int off = 2; off <= 16; off <<= 1) {
            a.x += __shfl_xor_sync(0xffffffffu, a.x, off);
            a.y += __shfl_xor_sync(0xffffffffu, a.y, off);
            a.z += __shfl_xor_sync(0xffffffffu, a.z, off);
            a.w += __shfl_xor_sync(0xffffffffu, a.w, off);
            b.x += __shfl_xor_sync(0xffffffffu, b.x, off);
            b.y += __shfl_xor_sync(0xffffffffu, b.y, off);
            b.z += __shfl_xor_sync(0xffffffffu, b.z, off);
            b.w += __shfl_xor_sync(0xffffffffu, b.w, off);
        }
        if (lane < 2) {
            int q0 = lane * 8;
            sBv[warp][q0 + 0] = a.x; sBv[warp][q0 + 1] = a.y;
            sBv[warp][q0 + 2] = a.z; sBv[warp][q0 + 3] = a.w;
            sBv[warp][q0 + 4] = b.x; sBv[warp][q0 + 5] = b.y;
            sBv[warp][q0 + 6] = b.z; sBv[warp][q0 + 7] = b.w;
        }
    }
    __syncthreads();

    // T: thread t -> (bc_local = t>>3, j = t&7), computes 16 p values
    int bcl = tid >> 3, j = tid & 7;
    float rv[QQ];
    #pragma unroll
    for (int q = 0; q < QQ; ++q) rv[q] = sBv[j][q];   // broadcast

    const float* kk = sK + bcl * (PP * QQ);
    float* tb = g_T + (size_t)(g * 32 + bcl) * PP * WW + (w0 + j);
    #pragma unroll
    for (int p = 0; p < PP; ++p) {
        float s = 0.f;
        #pragma unroll
        for (int q = 0; q < QQ; ++q) s = fmaf(kk[p * QQ + q], rv[q], s);  // broadcast
        tb[p * WW] = s;
    }
}

// ---------------------------------------------------------------------------
// Kernel C: out[bc,h,w] = sum_p Bu[h,p] * T[bc,p,w]
//   grid (H/ROWS=4, BC), 128 threads; thread t owns w = 4t..4t+3.
//   512 blocks, <=4/SM -> whole grid co-resident (no wave-2 tail).
//   Accumulator pairs packed over h; Bu = natural pair via broadcast LDS.128;
//   T dup'd once into 128 regs.
// ---------------------------------------------------------------------------
__global__ __launch_bounds__(128) void fused_stage(float* __restrict__ out) {
    int bc = blockIdx.y;
    int h0 = blockIdx.x * ROWS;
    int t = threadIdx.x;

    __shared__ float sBu[PP * ROWS];   // [p][hh], 8 KB

    // Stage Bu tile (coalesced float4 copy)
    {
        const float4* src = reinterpret_cast<const float4*>(g_But);
        float4* dst = reinterpret_cast<float4*>(sBu);
        #pragma unroll
        for (int i = t; i < PP * ROWS / 4; i += 128) {
            int p = i >> 5, c = i & 31;
            dst[i] = src[(p * HH + h0) / 4 + c];
        }
    }

    // Load T[p][4t..4t+3], duplicate into register pairs
    unsigned long long Td[PP][4];
    {
        const float4* t4 = reinterpret_cast<const float4*>(g_T + (size_t)bc * PP * WW);
        #pragma unroll
        for (int p = 0; p < PP; ++p) {
            float4 tl = t4[p * (WW / 4) + t];
            Td[p][0] = pk(tl.x, tl.x);
            Td[p][1] = pk(tl.y, tl.y);
            Td[p][2] = pk(tl.z, tl.z);
            Td[p][3] = pk(tl.w, tl.w);
        }
    }
    __syncthreads();

    float* obase = out + (size_t)bc * HH * WW + (size_t)h0 * WW + 4 * t;

    #pragma unroll 2
    for (int g = 0; g < ROWS; g += 4) {
        unsigned long long acc[4][2];
        #pragma unroll
        for (int w = 0; w < 4; ++w) { acc[w][0] = 0ull; acc[w][1] = 0ull; }

        #pragma unroll
        for (int p = 0; p < PP; ++p) {
            // Broadcast LDS.128: Bu rows h0+g..h0+g+3 as 2 natural (h,h+1) pairs
            ulonglong2 v = *reinterpret_cast<const ulonglong2*>(&sBu[p * ROWS + g]);
            fma2(acc[0][0], v.x, Td[p][0]);
            fma2(acc[1][0], v.x, Td[p][1]);
            fma2(acc[2][0], v.x, Td[p][2]);
            fma2(acc[3][0], v.x, Td[p][3]);
            fma2(acc[0][1], v.y, Td[p][0]);
            fma2(acc[1][1], v.y, Td[p][1]);
            fma2(acc[2][1], v.y, Td[p][2]);
            fma2(acc[3][1], v.y, Td[p][3]);
        }

        float r0[4], r1[4], r2[4], r3[4];
        #pragma unroll
        for (int w = 0; w < 4; ++w) {
            unpk(acc[w][0], r0[w], r1[w]);   // rows g, g+1
            unpk(acc[w][1], r2[w], r3[w]);   // rows g+2, g+3
        }
        __stcs(reinterpret_cast<float4*>(obase + (size_t)(g + 0) * WW), make_float4(r0[0], r0[1], r0[2], r0[3]));
        __stcs(reinterpret_cast<float4*>(obase + (size_t)(g + 1) * WW), make_float4(r1[0], r1[1], r1[2], r1[3]));
        __stcs(reinterpret_cast<float4*>(obase + (size_t)(g + 2) * WW), make_float4(r2[0], r2[1], r2[2], r2[3]));
        __stcs(reinterpret_cast<float4*>(obase + (size_t)(g + 3) * WW), make_float4(r3[0], r3[1], r3[2], r3[3]));
    }
}

// ---------------------------------------------------------------------------
extern "C" void kernel_launch(void* const* d_in, const int* in_sizes, int n_in,
                              void* d_out, int out_size) {
    const float* K     = (const float*)d_in[0];
    const float* basis = (const float*)d_in[1];
    float* out = (float*)d_out;
    (void)in_sizes; (void)n_in; (void)out_size;

    prepass<<<320, 256>>>(K, basis);

    dim3 g2(HH / ROWS, BC);
    fused_stage<<<g2, 128>>>(out);
}